// round 6
// baseline (speedup 1.0000x reference)
#include <cuda_runtime.h>
#include <cuda_bf16.h>
#include <cstdint>

#define ND 64
#define THREADS 384
#define TILE_S 32            // samples per CTA tile (192 rows, 12 warps x m16)
#define XPAD 776             // padded floats per sample in x staging (768+8)
#define DPAD 392             // padded floats per sample in d staging (384+8)

// ---- smem layout (bytes) ----
#define BF_OFF   0                    // uint4 [6 lv][12 j][4 p][32 lane] = 147456
#define BIAS_OFF 147456               // 192 floats
#define SCRX_OFF 148224               // 16 samples * 776 floats = 49664 B
#define SCRD_OFF (148224 + 49664)     // 197888; 16 * 392 * 4 = 25088 B
#define SMEM_BYTES (197888 + 25088)   // 222976

__device__ __forceinline__ uint32_t smem_u32(const void* p) {
    uint32_t a;
    asm("{ .reg .u64 t; cvta.to.shared.u64 t, %1; cvt.u32.u64 %0, t; }" : "=r"(a) : "l"(p));
    return a;
}

// fp32 -> (bf16 hi, bf16 lo) packed words; low half = first element
__device__ __forceinline__ void split_pk(float v0, float v1, uint32_t& hw, uint32_t& lw) {
    __nv_bfloat16 h0 = __float2bfloat16(v0), h1 = __float2bfloat16(v1);
    __nv_bfloat16 l0 = __float2bfloat16(v0 - __bfloat162float(h0));
    __nv_bfloat16 l1 = __float2bfloat16(v1 - __bfloat162float(h1));
    hw = (uint32_t)__bfloat16_as_ushort(h0) | ((uint32_t)__bfloat16_as_ushort(h1) << 16);
    lw = (uint32_t)__bfloat16_as_ushort(l0) | ((uint32_t)__bfloat16_as_ushort(l1) << 16);
}

__device__ __forceinline__ void mma4(float* c, const uint32_t* a, uint32_t b0, uint32_t b1) {
    asm volatile(
        "mma.sync.aligned.m16n8k16.row.col.f32.bf16.bf16.f32 "
        "{%0,%1,%2,%3}, {%4,%5,%6,%7}, {%8,%9}, {%0,%1,%2,%3};"
        : "+f"(c[0]), "+f"(c[1]), "+f"(c[2]), "+f"(c[3])
        : "r"(a[0]), "r"(a[1]), "r"(a[2]), "r"(a[3]), "r"(b0), "r"(b1));
}

__device__ __forceinline__ void cp16(uint32_t dst, const void* src) {
    asm volatile("cp.async.cg.shared.global [%0], [%1], 16;" :: "r"(dst), "l"(src));
}
__device__ __forceinline__ void cp_commit() {
    asm volatile("cp.async.commit_group;" ::: "memory");
}
__device__ __forceinline__ void cp_wait0() {
    asm volatile("cp.async.wait_group 0;" ::: "memory");
}

// copy one 16-sample chunk (x + d) into padded staging, via cp.async
__device__ __forceinline__ void issue_chunk(const float* __restrict__ x,
                                            const float* __restrict__ dd,
                                            int n, int sA,
                                            uint32_t scx_u, uint32_t scd_u, int tid) {
    const int csn = min(16, n - sA);
    if (csn <= 0) return;
    {
        const float4* xs = (const float4*)(x + (size_t)sA * 768);
        const int cnt = csn * 192;
        for (int i4 = tid; i4 < cnt; i4 += THREADS) {
            int sl = i4 / 192, f = i4 - sl * 192;
            cp16(scx_u + (uint32_t)(sl * XPAD + f * 4) * 4u, xs + (size_t)sl * 192 + f);
        }
    }
    {
        const float4* ds = (const float4*)(dd + (size_t)sA * 384);
        const int cnt = csn * 96;
        for (int i4 = tid; i4 < cnt; i4 += THREADS) {
            int sl = i4 / 96, f = i4 - sl * 96;
            cp16(scd_u + (uint32_t)(sl * DPAD + f * 4) * 4u, ds + (size_t)sl * 96 + f);
        }
    }
}

__global__ __launch_bounds__(THREADS, 1)
void dijet_mma(const float* __restrict__ x, const float* __restrict__ dd,
               const float* __restrict__ W1, const float* __restrict__ b1,
               const float* __restrict__ W2, const float* __restrict__ b2,
               const float* __restrict__ W3, const float* __restrict__ b3,
               float* __restrict__ out, int n) {
    extern __shared__ char smem[];
    uint4*  Bfr  = (uint4*)(smem + BF_OFF);
    float*  bias = (float*)(smem + BIAS_OFF);
    float*  scx  = (float*)(smem + SCRX_OFF);
    float*  scd  = (float*)(smem + SCRD_OFF);
    const uint32_t scx_u = smem_u32(scx);
    const uint32_t scd_u = smem_u32(scd);

    const int tid  = threadIdx.x;
    const int w    = tid >> 5;
    const int lane = tid & 31;
    const int g    = lane >> 2;     // row-in-frag 0..7
    const int c    = lane & 3;      // k/n sub-index

    if (tid < 64) { bias[tid] = b1[tid]; bias[64 + tid] = b2[tid]; bias[128 + tid] = b3[tid]; }

    // ==== stage weights once: fp32 [o][i][k] -> bf16 hi/lo fragments ====
    {
        const float* Wg[3] = {W1, W2, W3};
        float* scr = scx;     // bounce buffer (24576 B, fits in x staging region)
        for (int l = 0; l < 3; ++l) {
            for (int oh = 0; oh < 2; ++oh) {
                __syncthreads();
                const float4* src = (const float4*)(Wg[l] + oh * 32 * 192);
                float4* dst = (float4*)scr;
                for (int i4 = tid; i4 < 1536; i4 += THREADS) dst[i4] = src[i4];
                __syncthreads();
#pragma unroll
                for (int q = 0; q < 2; ++q) {
                    int cmb = w * 2 + q;            // 0..23
                    int j = cmb >> 1, pp = cmb & 1, p = oh * 2 + pp;
                    int nl0 = pp * 16 + g, nl1 = nl0 + 8;
                    int k0 = j * 16 + 2 * c;
                    int blk = k0 >> 6, i0 = k0 & 63;
                    const float* s0p = scr + nl0 * 192 + blk;
                    const float* s1p = scr + nl1 * 192 + blk;
                    uint32_t h0, l0, h1, l1, h2, l2, h3, l3;
                    split_pk(s0p[i0 * 3],       s0p[(i0 + 1) * 3], h0, l0);
                    split_pk(s0p[(i0 + 8) * 3], s0p[(i0 + 9) * 3], h1, l1);
                    split_pk(s1p[i0 * 3],       s1p[(i0 + 1) * 3], h2, l2);
                    split_pk(s1p[(i0 + 8) * 3], s1p[(i0 + 9) * 3], h3, l3);
                    Bfr[(((l * 2 + 0) * 12 + j) * 4 + p) * 32 + lane] = make_uint4(h0, h1, h2, h3);
                    Bfr[(((l * 2 + 1) * 12 + j) * 4 + p) * 32 + lane] = make_uint4(l0, l1, l2, l3);
                }
            }
        }
        __syncthreads();
    }

    const int ntiles = (n + TILE_S - 1) / TILE_S;
    int tile = blockIdx.x;
    if (tile < ntiles) issue_chunk(x, dd, n, tile * TILE_S, scx_u, scd_u, tid);
    cp_commit();

    // my chunk half and chunk-local row mapping
    const int half = (w >= 6) ? 1 : 0;
    const int clr  = (w - half * 6) * 16 + g;          // 0..95
    const int sl   = clr / 6,  slot  = clr - sl * 6;
    const int clr2 = clr + 8;
    const int sl2  = clr2 / 6, slot2 = clr2 - sl2 * 6;

    for (; tile < ntiles; tile += gridDim.x) {
        const int s0 = tile * TILE_S;

        uint32_t Ahx[8][4], Alx[8][4], Ahd[4][4], Ald[4][4];

        // ==== two chunk phases: A (warps 0-5) then B (warps 6-11) ====
#pragma unroll
        for (int ph = 0; ph < 2; ++ph) {
            cp_wait0();
            __syncthreads();
            if (half == ph) {
                const int sA  = s0 + ph * 16;
                const int csn = min(16, n - sA);
                const bool v0 = sl < csn, v1 = sl2 < csn;
                const float* r0p = scx + sl  * XPAD + 2 * slot;
                const float* r1p = scx + sl2 * XPAD + 2 * slot2;
#pragma unroll
                for (int j = 0; j < 8; ++j) {
                    const int blk = j >> 2;
                    const int i0 = (j & 3) * 16 + 2 * c;
                    const float* q0 = r0p + blk;
                    const float* q1 = r1p + blk;
                    float e00 = v0 ? q0[i0 * 12]       : 0.f;
                    float e01 = v0 ? q0[(i0 + 1) * 12] : 0.f;
                    float e02 = v0 ? q0[(i0 + 8) * 12] : 0.f;
                    float e03 = v0 ? q0[(i0 + 9) * 12] : 0.f;
                    float e10 = v1 ? q1[i0 * 12]       : 0.f;
                    float e11 = v1 ? q1[(i0 + 1) * 12] : 0.f;
                    float e12 = v1 ? q1[(i0 + 8) * 12] : 0.f;
                    float e13 = v1 ? q1[(i0 + 9) * 12] : 0.f;
                    split_pk(e00, e01, Ahx[j][0], Alx[j][0]);
                    split_pk(e10, e11, Ahx[j][1], Alx[j][1]);
                    split_pk(e02, e03, Ahx[j][2], Alx[j][2]);
                    split_pk(e12, e13, Ahx[j][3], Alx[j][3]);
                }
                const float* d0p = scd + sl  * DPAD + slot;
                const float* d1p = scd + sl2 * DPAD + slot2;
#pragma unroll
                for (int jd = 0; jd < 4; ++jd) {
                    const int i0 = jd * 16 + 2 * c;
                    float e00 = v0 ? d0p[i0 * 6]       : 0.f;
                    float e01 = v0 ? d0p[(i0 + 1) * 6] : 0.f;
                    float e02 = v0 ? d0p[(i0 + 8) * 6] : 0.f;
                    float e03 = v0 ? d0p[(i0 + 9) * 6] : 0.f;
                    float e10 = v1 ? d1p[i0 * 6]       : 0.f;
                    float e11 = v1 ? d1p[(i0 + 1) * 6] : 0.f;
                    float e12 = v1 ? d1p[(i0 + 8) * 6] : 0.f;
                    float e13 = v1 ? d1p[(i0 + 9) * 6] : 0.f;
                    split_pk(e00, e01, Ahd[jd][0], Ald[jd][0]);
                    split_pk(e10, e11, Ahd[jd][1], Ald[jd][1]);
                    split_pk(e02, e03, Ahd[jd][2], Ald[jd][2]);
                    split_pk(e12, e13, Ahd[jd][3], Ald[jd][3]);
                }
            }
            __syncthreads();
            // issue next copy: phase 0 -> chunk B of this tile; phase 1 -> chunk A of next tile
            if (ph == 0) {
                issue_chunk(x, dd, n, s0 + 16, scx_u, scd_u, tid);
            } else {
                int nxt = tile + gridDim.x;
                if (nxt < ntiles) issue_chunk(x, dd, n, nxt * TILE_S, scx_u, scd_u, tid);
            }
            cp_commit();
        }

        float acc[8][4];
#pragma unroll
        for (int nt = 0; nt < 8; ++nt)
#pragma unroll
            for (int e = 0; e < 4; ++e) acc[nt][e] = 0.f;

        // ==== 3 chained layers (next-tile copy in flight underneath) ====
#pragma unroll
        for (int l = 0; l < 3; ++l) {
#pragma unroll
            for (int j = 0; j < 12; ++j) {
                const uint32_t* Ah = (j < 8) ? Ahx[j] : Ahd[j - 8];
                const uint32_t* Al = (j < 8) ? Alx[j] : Ald[j - 8];
                const uint4* bhp = Bfr + (((l * 2 + 0) * 12 + j) * 4) * 32 + lane;
                const uint4* blp = Bfr + (((l * 2 + 1) * 12 + j) * 4) * 32 + lane;
#pragma unroll
                for (int p = 0; p < 4; ++p) {
                    uint4 bh = bhp[p * 32];
                    uint4 bl = blp[p * 32];
                    mma4(acc[2 * p],     Ah, bh.x, bh.y);
                    mma4(acc[2 * p],     Ah, bl.x, bl.y);
                    mma4(acc[2 * p],     Al, bh.x, bh.y);
                    mma4(acc[2 * p + 1], Ah, bh.z, bh.w);
                    mma4(acc[2 * p + 1], Ah, bl.z, bl.w);
                    mma4(acc[2 * p + 1], Al, bh.z, bh.w);
                }
            }
            if (l < 2) {
                // D -> next-layer d fragments, register-local (o dim == next k dim)
#pragma unroll
                for (int jd = 0; jd < 4; ++jd) {
                    const int o0 = jd * 16 + 2 * c;
                    float bb0 = bias[l * 64 + o0],     bb1 = bias[l * 64 + o0 + 1];
                    float bb8 = bias[l * 64 + o0 + 8], bb9 = bias[l * 64 + o0 + 9];
                    float t0 = fmaxf(acc[2 * jd][0] + bb0, 0.f);
                    float t1 = fmaxf(acc[2 * jd][1] + bb1, 0.f);
                    float t2 = fmaxf(acc[2 * jd][2] + bb0, 0.f);
                    float t3 = fmaxf(acc[2 * jd][3] + bb1, 0.f);
                    float u0 = fmaxf(acc[2 * jd + 1][0] + bb8, 0.f);
                    float u1 = fmaxf(acc[2 * jd + 1][1] + bb9, 0.f);
                    float u2 = fmaxf(acc[2 * jd + 1][2] + bb8, 0.f);
                    float u3 = fmaxf(acc[2 * jd + 1][3] + bb9, 0.f);
                    split_pk(t0, t1, Ahd[jd][0], Ald[jd][0]);
                    split_pk(t2, t3, Ahd[jd][1], Ald[jd][1]);
                    split_pk(u0, u1, Ahd[jd][2], Ald[jd][2]);
                    split_pk(u2, u3, Ahd[jd][3], Ald[jd][3]);
#pragma unroll
                    for (int e = 0; e < 4; ++e) {
                        acc[2 * jd][e] = 0.f;
                        acc[2 * jd + 1][e] = 0.f;
                    }
                }
            }
        }

        // ==== final epilogue: relu(D + b3 + d1) -> gmem ====
        {
            const long rmax = (long)n * 6;
            const long r0 = (long)s0 * 6 + w * 16 + g;
            const long r1 = r0 + 8;
            const bool v0 = r0 < rmax, v1 = r1 < rmax;
            const int  sa0 = (int)(r0 / 6), sl0 = (int)(r0 - (long)sa0 * 6);
            const int  sa1 = (int)(r1 / 6), sl1 = (int)(r1 - (long)sa1 * 6);
            const size_t base0 = (size_t)sa0 * 384 + sl0;
            const size_t base1 = (size_t)sa1 * 384 + sl1;
#pragma unroll
            for (int nt = 0; nt < 8; ++nt) {
                const int o0 = nt * 8 + 2 * c;
                const float bb0 = bias[128 + o0], bb1 = bias[128 + o0 + 1];
                if (v0) {
                    size_t a00 = base0 + (size_t)o0 * 6, a01 = a00 + 6;
                    out[a00] = fmaxf(acc[nt][0] + bb0 + dd[a00], 0.f);
                    out[a01] = fmaxf(acc[nt][1] + bb1 + dd[a01], 0.f);
                }
                if (v1) {
                    size_t a10 = base1 + (size_t)o0 * 6, a11 = a10 + 6;
                    out[a10] = fmaxf(acc[nt][2] + bb0 + dd[a10], 0.f);
                    out[a11] = fmaxf(acc[nt][3] + bb1 + dd[a11], 0.f);
                }
            }
        }
    }
}

extern "C" void kernel_launch(void* const* d_in, const int* in_sizes, int n_in,
                              void* d_out, int out_size) {
    const float* x  = (const float*)d_in[0];
    const float* dd = (const float*)d_in[1];
    const float* W1 = (const float*)d_in[2];
    const float* b1 = (const float*)d_in[3];
    const float* W2 = (const float*)d_in[4];
    const float* b2 = (const float*)d_in[5];
    const float* W3 = (const float*)d_in[6];
    const float* b3 = (const float*)d_in[7];
    float* out = (float*)d_out;

    const int n = in_sizes[0] / (ND * 12);

    int sms = 148;
    cudaDeviceGetAttribute(&sms, cudaDevAttrMultiProcessorCount, 0);
    cudaFuncSetAttribute(dijet_mma, cudaFuncAttributeMaxDynamicSharedMemorySize, SMEM_BYTES);

    dijet_mma<<<sms, THREADS, SMEM_BYTES>>>(x, dd, W1, b1, W2, b2, W3, b3, out, n);
}

// round 7
// speedup vs baseline: 1.3396x; 1.3396x over previous
#include <cuda_runtime.h>
#include <cuda_bf16.h>
#include <cstdint>

#define ND 64
#define THREADS 384
#define TILE_R 192           // rows per CTA tile (12 warps x m16)

// ---- smem layout (bytes) ----
#define BF_OFF   0                    // uint4 [6 lv][12 j][4 p][32 lane] = 147456
#define BIAS_OFF 147456               // 192 floats = 768
#define SCR_OFF  148224               // weight-staging bounce: 6144 floats = 24576 B
#define SMEM_BYTES (148224 + 24576)   // 172800

// fp32 -> (bf16 hi, bf16 lo) packed words; low half = first element
__device__ __forceinline__ void split_pk(float v0, float v1, uint32_t& hw, uint32_t& lw) {
    __nv_bfloat16 h0 = __float2bfloat16(v0), h1 = __float2bfloat16(v1);
    __nv_bfloat16 l0 = __float2bfloat16(v0 - __bfloat162float(h0));
    __nv_bfloat16 l1 = __float2bfloat16(v1 - __bfloat162float(h1));
    hw = (uint32_t)__bfloat16_as_ushort(h0) | ((uint32_t)__bfloat16_as_ushort(h1) << 16);
    lw = (uint32_t)__bfloat16_as_ushort(l0) | ((uint32_t)__bfloat16_as_ushort(l1) << 16);
}

__device__ __forceinline__ void mma4(float* c, const uint32_t* a, uint32_t b0, uint32_t b1) {
    asm volatile(
        "mma.sync.aligned.m16n8k16.row.col.f32.bf16.bf16.f32 "
        "{%0,%1,%2,%3}, {%4,%5,%6,%7}, {%8,%9}, {%0,%1,%2,%3};"
        : "+f"(c[0]), "+f"(c[1]), "+f"(c[2]), "+f"(c[3])
        : "r"(a[0]), "r"(a[1]), "r"(a[2]), "r"(a[3]), "r"(b0), "r"(b1));
}

__global__ __launch_bounds__(THREADS, 1)
void dijet_mma(const float* __restrict__ x, const float* __restrict__ dd,
               const float* __restrict__ W1, const float* __restrict__ b1,
               const float* __restrict__ W2, const float* __restrict__ b2,
               const float* __restrict__ W3, const float* __restrict__ b3,
               float* __restrict__ out, int n) {
    extern __shared__ char smem[];
    uint4*  Bfr  = (uint4*)(smem + BF_OFF);
    float*  bias = (float*)(smem + BIAS_OFF);
    float*  scr  = (float*)(smem + SCR_OFF);

    const int tid  = threadIdx.x;
    const int w    = tid >> 5;
    const int lane = tid & 31;
    const int g    = lane >> 2;     // row-in-frag 0..7
    const int c    = lane & 3;      // k/n sub-index

    if (tid < 64) { bias[tid] = b1[tid]; bias[64 + tid] = b2[tid]; bias[128 + tid] = b3[tid]; }

    // ==== stage weights once: fp32 [o][i][k] -> bf16 hi/lo fragments ====
    {
        const float* Wg[3] = {W1, W2, W3};
        for (int l = 0; l < 3; ++l) {
            for (int oh = 0; oh < 2; ++oh) {
                __syncthreads();
                const float4* src = (const float4*)(Wg[l] + oh * 32 * 192);
                float4* dst = (float4*)scr;
                for (int i4 = tid; i4 < 1536; i4 += THREADS) dst[i4] = src[i4];
                __syncthreads();
#pragma unroll
                for (int q = 0; q < 2; ++q) {
                    int cmb = w * 2 + q;            // 0..23
                    int j = cmb >> 1, pp = cmb & 1, p = oh * 2 + pp;
                    int nl0 = pp * 16 + g, nl1 = nl0 + 8;
                    int k0 = j * 16 + 2 * c;
                    int blk = k0 >> 6, i0 = k0 & 63;
                    const float* s0p = scr + nl0 * 192 + blk;
                    const float* s1p = scr + nl1 * 192 + blk;
                    uint32_t h0, l0, h1, l1, h2, l2, h3, l3;
                    split_pk(s0p[i0 * 3],       s0p[(i0 + 1) * 3], h0, l0);
                    split_pk(s0p[(i0 + 8) * 3], s0p[(i0 + 9) * 3], h1, l1);
                    split_pk(s1p[i0 * 3],       s1p[(i0 + 1) * 3], h2, l2);
                    split_pk(s1p[(i0 + 8) * 3], s1p[(i0 + 9) * 3], h3, l3);
                    Bfr[(((l * 2 + 0) * 12 + j) * 4 + p) * 32 + lane] = make_uint4(h0, h1, h2, h3);
                    Bfr[(((l * 2 + 1) * 12 + j) * 4 + p) * 32 + lane] = make_uint4(l0, l1, l2, l3);
                }
            }
        }
        __syncthreads();   // last barrier: Bfr/bias read-only from here on
    }

    const long rmax   = (long)n * 6;
    const int  ntiles = (int)((rmax + TILE_R - 1) / TILE_R);

    for (int tile = blockIdx.x; tile < ntiles; tile += gridDim.x) {
        const long base = (long)tile * TILE_R;

        // warp-owned rows: r0 = base + w*16 + g, r1 = r0 + 8
        const long r0 = base + w * 16 + g;
        const long r1 = r0 + 8;
        const bool v0 = r0 < rmax, v1 = r1 < rmax;
        const int  sa0 = (int)(r0 / 6), sl0 = (int)(r0 - (long)sa0 * 6);
        const int  sa1 = (int)(r1 / 6), sl1 = (int)(r1 - (long)sa1 * 6);

        uint32_t Ahx[8][4], Alx[8][4], Ahd[4][4], Ald[4][4];

        // ==== direct gmem gather -> A fragments (no smem, no barriers) ====
        {
            const float* px0 = x + (size_t)sa0 * 768 + 2 * sl0;
            const float* px1 = x + (size_t)sa1 * 768 + 2 * sl1;
#pragma unroll
            for (int j = 0; j < 8; ++j) {
                const int blk = j >> 2;              // 0 = xe, 1 = xo
                const int i0 = (j & 3) * 16 + 2 * c;
                const float* q0 = px0 + blk;
                const float* q1 = px1 + blk;
                float e00 = v0 ? __ldg(q0 + i0 * 12)       : 0.f;
                float e01 = v0 ? __ldg(q0 + (i0 + 1) * 12) : 0.f;
                float e02 = v0 ? __ldg(q0 + (i0 + 8) * 12) : 0.f;
                float e03 = v0 ? __ldg(q0 + (i0 + 9) * 12) : 0.f;
                float e10 = v1 ? __ldg(q1 + i0 * 12)       : 0.f;
                float e11 = v1 ? __ldg(q1 + (i0 + 1) * 12) : 0.f;
                float e12 = v1 ? __ldg(q1 + (i0 + 8) * 12) : 0.f;
                float e13 = v1 ? __ldg(q1 + (i0 + 9) * 12) : 0.f;
                split_pk(e00, e01, Ahx[j][0], Alx[j][0]);
                split_pk(e10, e11, Ahx[j][1], Alx[j][1]);
                split_pk(e02, e03, Ahx[j][2], Alx[j][2]);
                split_pk(e12, e13, Ahx[j][3], Alx[j][3]);
            }
            const float* d0p = dd + (size_t)sa0 * 384 + sl0;
            const float* d1p = dd + (size_t)sa1 * 384 + sl1;
#pragma unroll
            for (int jd = 0; jd < 4; ++jd) {
                const int i0 = jd * 16 + 2 * c;
                float e00 = v0 ? __ldg(d0p + i0 * 6)       : 0.f;
                float e01 = v0 ? __ldg(d0p + (i0 + 1) * 6) : 0.f;
                float e02 = v0 ? __ldg(d0p + (i0 + 8) * 6) : 0.f;
                float e03 = v0 ? __ldg(d0p + (i0 + 9) * 6) : 0.f;
                float e10 = v1 ? __ldg(d1p + i0 * 6)       : 0.f;
                float e11 = v1 ? __ldg(d1p + (i0 + 1) * 6) : 0.f;
                float e12 = v1 ? __ldg(d1p + (i0 + 8) * 6) : 0.f;
                float e13 = v1 ? __ldg(d1p + (i0 + 9) * 6) : 0.f;
                split_pk(e00, e01, Ahd[jd][0], Ald[jd][0]);
                split_pk(e10, e11, Ahd[jd][1], Ald[jd][1]);
                split_pk(e02, e03, Ahd[jd][2], Ald[jd][2]);
                split_pk(e12, e13, Ahd[jd][3], Ald[jd][3]);
            }
        }

        float acc[8][4];
#pragma unroll
        for (int nt = 0; nt < 8; ++nt)
#pragma unroll
            for (int e = 0; e < 4; ++e) acc[nt][e] = 0.f;

        // ==== 3 chained layers ====
#pragma unroll
        for (int l = 0; l < 3; ++l) {
#pragma unroll
            for (int j = 0; j < 12; ++j) {
                const uint32_t* Ah = (j < 8) ? Ahx[j] : Ahd[j - 8];
                const uint32_t* Al = (j < 8) ? Alx[j] : Ald[j - 8];
                const uint4* bhp = Bfr + (((l * 2 + 0) * 12 + j) * 4) * 32 + lane;
                const uint4* blp = Bfr + (((l * 2 + 1) * 12 + j) * 4) * 32 + lane;
#pragma unroll
                for (int p = 0; p < 4; ++p) {
                    uint4 bh = bhp[p * 32];
                    uint4 bl = blp[p * 32];
                    mma4(acc[2 * p],     Ah, bh.x, bh.y);
                    mma4(acc[2 * p + 1], Ah, bh.z, bh.w);
                    mma4(acc[2 * p],     Ah, bl.x, bl.y);
                    mma4(acc[2 * p + 1], Ah, bl.z, bl.w);
                    mma4(acc[2 * p],     Al, bh.x, bh.y);
                    mma4(acc[2 * p + 1], Al, bh.z, bh.w);
                }
            }
            if (l < 2) {
                // D -> next-layer d fragments, register-local (o dim == next k dim)
#pragma unroll
                for (int jd = 0; jd < 4; ++jd) {
                    const int o0 = jd * 16 + 2 * c;
                    float bb0 = bias[l * 64 + o0],     bb1 = bias[l * 64 + o0 + 1];
                    float bb8 = bias[l * 64 + o0 + 8], bb9 = bias[l * 64 + o0 + 9];
                    float t0 = fmaxf(acc[2 * jd][0] + bb0, 0.f);
                    float t1 = fmaxf(acc[2 * jd][1] + bb1, 0.f);
                    float t2 = fmaxf(acc[2 * jd][2] + bb0, 0.f);
                    float t3 = fmaxf(acc[2 * jd][3] + bb1, 0.f);
                    float u0 = fmaxf(acc[2 * jd + 1][0] + bb8, 0.f);
                    float u1 = fmaxf(acc[2 * jd + 1][1] + bb9, 0.f);
                    float u2 = fmaxf(acc[2 * jd + 1][2] + bb8, 0.f);
                    float u3 = fmaxf(acc[2 * jd + 1][3] + bb9, 0.f);
                    split_pk(t0, t1, Ahd[jd][0], Ald[jd][0]);
                    split_pk(t2, t3, Ahd[jd][1], Ald[jd][1]);
                    split_pk(u0, u1, Ahd[jd][2], Ald[jd][2]);
                    split_pk(u2, u3, Ahd[jd][3], Ald[jd][3]);
#pragma unroll
                    for (int e = 0; e < 4; ++e) {
                        acc[2 * jd][e] = 0.f;
                        acc[2 * jd + 1][e] = 0.f;
                    }
                }
            }
        }

        // ==== final epilogue: relu(D + b3 + d1) -> gmem ====
        {
            const size_t base0 = (size_t)sa0 * 384 + sl0;
            const size_t base1 = (size_t)sa1 * 384 + sl1;
#pragma unroll
            for (int nt = 0; nt < 8; ++nt) {
                const int o0 = nt * 8 + 2 * c;
                const float bb0 = bias[128 + o0], bb1 = bias[128 + o0 + 1];
                if (v0) {
                    size_t a00 = base0 + (size_t)o0 * 6, a01 = a00 + 6;
                    out[a00] = fmaxf(acc[nt][0] + bb0 + dd[a00], 0.f);
                    out[a01] = fmaxf(acc[nt][1] + bb1 + dd[a01], 0.f);
                }
                if (v1) {
                    size_t a10 = base1 + (size_t)o0 * 6, a11 = a10 + 6;
                    out[a10] = fmaxf(acc[nt][2] + bb0 + dd[a10], 0.f);
                    out[a11] = fmaxf(acc[nt][3] + bb1 + dd[a11], 0.f);
                }
            }
        }
    }
}

extern "C" void kernel_launch(void* const* d_in, const int* in_sizes, int n_in,
                              void* d_out, int out_size) {
    const float* x  = (const float*)d_in[0];
    const float* dd = (const float*)d_in[1];
    const float* W1 = (const float*)d_in[2];
    const float* b1 = (const float*)d_in[3];
    const float* W2 = (const float*)d_in[4];
    const float* b2 = (const float*)d_in[5];
    const float* W3 = (const float*)d_in[6];
    const float* b3 = (const float*)d_in[7];
    float* out = (float*)d_out;

    const int n = in_sizes[0] / (ND * 12);

    int sms = 148;
    cudaDeviceGetAttribute(&sms, cudaDevAttrMultiProcessorCount, 0);
    cudaFuncSetAttribute(dijet_mma, cudaFuncAttributeMaxDynamicSharedMemorySize, SMEM_BYTES);

    dijet_mma<<<sms, THREADS, SMEM_BYTES>>>(x, dd, W1, b1, W2, b2, W3, b3, out, n);
}